// round 8
// baseline (speedup 1.0000x reference)
#include <cuda_runtime.h>
#include <math.h>

// Problem constants
#define B_   16
#define C_   256
#define HH_  64
#define WW_  64
#define N_   4096      // HH*WW
#define K_   16
#define H_   4
#define U_   4
#define R_   23
#define DV_  64
#define EPS_ 1e-3f

// Scratch (device globals; no allocation allowed)
__device__ float  g_wfold[384 * 256];
__device__ float  g_bias[384];
__device__ float  g_proj[(size_t)B_ * 384 * N_];          // rows 0-63 q, 64-127 k, 128-383 v
__device__ float  g_LcPart[(size_t)B_ * 32 * 1024];
__device__ float  g_Lc[B_ * K_ * DV_];                    // [b][k][dv]
__device__ float2 g_tw[64];                               // fwd twiddles W_128^j
__device__ float4 g_W3[1472 * 65];                        // [row=k*92+u*23+dy][f]: (c, d-c, c+d, 0)
__device__ float2 g_Rhat[(size_t)262144 * 65];            // [(b*64+dv)*4+u][y][f]

// ---- packed fp32x2 helpers (proj GEMM) -------------------------------------
__device__ __forceinline__ unsigned long long pk2(float lo, float hi) {
    unsigned long long r;
    asm("mov.b64 %0, {%1, %2};" : "=l"(r) : "f"(lo), "f"(hi));
    return r;
}
__device__ __forceinline__ void ffma2(unsigned long long& d, unsigned long long a,
                                      unsigned long long b) {
    asm("fma.rn.f32x2 %0, %1, %2, %0;" : "+l"(d) : "l"(a), "l"(b));
}
__device__ __forceinline__ float2 upk2(unsigned long long v) {
    float2 r;
    asm("mov.b64 {%0, %1}, %2;" : "=f"(r.x), "=f"(r.y) : "l"(v));
    return r;
}

// ---------------------------------------------------------------------------
// warp-cooperative in-place 128-pt complex FFT (DIT radix-2, natural order)
// ---------------------------------------------------------------------------
__device__ __forceinline__ void warp_fft128(float2* ln, int lane) {
    __syncwarp();
    float2 a0 = ln[lane], a1 = ln[lane + 32], a2 = ln[lane + 64], a3 = ln[lane + 96];
    __syncwarp();
    ln[__brev((unsigned)lane) >> 25]        = a0;
    ln[__brev((unsigned)(lane + 32)) >> 25] = a1;
    ln[__brev((unsigned)(lane + 64)) >> 25] = a2;
    ln[__brev((unsigned)(lane + 96)) >> 25] = a3;
    __syncwarp();
#pragma unroll
    for (int s = 0; s < 7; s++) {
        int half = 1 << s;
#pragma unroll
        for (int t = 0; t < 2; t++) {
            int bf  = lane + t * 32;
            int grp = bf >> s;
            int pos = bf & (half - 1);
            int i0  = (grp << (s + 1)) + pos;
            int i1  = i0 + half;
            float2 w = g_tw[pos << (6 - s)];
            float2 a = ln[i0], b = ln[i1];
            float2 bt = make_float2(b.x * w.x - b.y * w.y, b.x * w.y + b.y * w.x);
            ln[i0] = make_float2(a.x + bt.x, a.y + bt.y);
            ln[i1] = make_float2(a.x - bt.x, a.y - bt.y);
        }
        __syncwarp();
    }
}

__global__ void twiddle_kernel() {
    int j = threadIdx.x;
    if (j < 64) {
        double ang = -2.0 * 3.14159265358979323846 * (double)j / 128.0;
        g_tw[j] = make_float2((float)cos(ang), (float)sin(ang));
    }
}

// ---------------------------------------------------------------------------
// K1: fold BN into projection weights
// ---------------------------------------------------------------------------
__global__ void fold_kernel(const float* __restrict__ w_q, const float* __restrict__ w_k,
                            const float* __restrict__ w_v,
                            const float* __restrict__ gq, const float* __restrict__ bq,
                            const float* __restrict__ mq, const float* __restrict__ vq,
                            const float* __restrict__ gv, const float* __restrict__ bv,
                            const float* __restrict__ mv, const float* __restrict__ vvar) {
    int o = blockIdx.x * blockDim.x + threadIdx.x;
    if (o >= 384) return;
    if (o < 64) {
        float inv = gq[o] * rsqrtf(vq[o] + EPS_);
        g_bias[o] = bq[o] - mq[o] * inv;
        for (int c = 0; c < 256; c++) g_wfold[o * 256 + c] = w_q[o * 256 + c] * inv;
    } else if (o < 128) {
        int i = o - 64;
        g_bias[o] = 0.f;
        for (int c = 0; c < 256; c++) g_wfold[o * 256 + c] = w_k[i * 256 + c];
    } else {
        int i = o - 128;
        float inv = gv[i] * rsqrtf(vvar[i] + EPS_);
        g_bias[o] = bv[i] - mv[i] * inv;
        for (int c = 0; c < 256; c++) g_wfold[o * 256 + c] = w_v[i * 256 + c] * inv;
    }
}

// ---------------------------------------------------------------------------
// K2: projection GEMM
// ---------------------------------------------------------------------------
__global__ __launch_bounds__(256) void proj_gemm_kernel(const float* __restrict__ x) {
    __shared__ float As[16][64];
    __shared__ float Bs[16][128];
    const int b  = blockIdx.z;
    const int m0 = blockIdx.y * 64;
    const int n0 = blockIdx.x * 128;
    const int tid = threadIdx.x;
    const int tx = tid & 15, ty = tid >> 4;
    const float* xb = x + (size_t)b * C_ * N_ + n0;

    unsigned long long acc[4][4];
#pragma unroll
    for (int j = 0; j < 4; j++)
#pragma unroll
        for (int i = 0; i < 4; i++) acc[j][i] = 0ull;

    for (int k0 = 0; k0 < 256; k0 += 16) {
#pragma unroll
        for (int l = 0; l < 4; l++) {
            int e = tid + l * 256;
            int m = e & 63, kk = e >> 6;
            As[kk][m] = g_wfold[(m0 + m) * 256 + k0 + kk];
        }
#pragma unroll
        for (int l = 0; l < 8; l++) {
            int e = tid + l * 256;
            int kk = e >> 7, n = e & 127;
            Bs[kk][n] = xb[(size_t)(k0 + kk) * N_ + n];
        }
        __syncthreads();
#pragma unroll
        for (int kk = 0; kk < 16; kk++) {
            float4 a4 = *(const float4*)&As[kk][ty * 4];
            float4 b0 = *(const float4*)&Bs[kk][tx * 8];
            float4 b1 = *(const float4*)&Bs[kk][tx * 8 + 4];
            unsigned long long bp[4] = {pk2(b0.x, b0.y), pk2(b0.z, b0.w),
                                        pk2(b1.x, b1.y), pk2(b1.z, b1.w)};
            float av[4] = {a4.x, a4.y, a4.z, a4.w};
#pragma unroll
            for (int j = 0; j < 4; j++) {
                unsigned long long ap = pk2(av[j], av[j]);
#pragma unroll
                for (int i = 0; i < 4; i++) ffma2(acc[j][i], ap, bp[i]);
            }
        }
        __syncthreads();
    }
#pragma unroll
    for (int j = 0; j < 4; j++) {
        int m = m0 + ty * 4 + j;
        float bi = g_bias[m];
        float* dst = g_proj + ((size_t)b * 384 + m) * N_ + n0 + tx * 8;
#pragma unroll
        for (int i = 0; i < 4; i++) {
            float2 v = upk2(acc[j][i]);
            dst[i * 2]     = v.x + bi;
            dst[i * 2 + 1] = v.y + bi;
        }
    }
}

// ---------------------------------------------------------------------------
// K3: softmax over positions for k rows
// ---------------------------------------------------------------------------
__global__ __launch_bounds__(256) void softmax_kernel() {
    __shared__ float red[8];
    const int row = blockIdx.x;
    const int b = row >> 6, r = row & 63;
    float* p = g_proj + ((size_t)b * 384 + 64 + r) * N_;
    const int tid = threadIdx.x, lane = tid & 31, wid = tid >> 5;

    float v[16];
    float mx = -3.4e38f;
#pragma unroll
    for (int l = 0; l < 16; l++) {
        v[l] = p[tid + l * 256];
        mx = fmaxf(mx, v[l]);
    }
#pragma unroll
    for (int o = 16; o; o >>= 1) mx = fmaxf(mx, __shfl_xor_sync(0xffffffffu, mx, o));
    if (!lane) red[wid] = mx;
    __syncthreads();
    mx = red[0];
#pragma unroll
    for (int w = 1; w < 8; w++) mx = fmaxf(mx, red[w]);

    float s = 0.f;
#pragma unroll
    for (int l = 0; l < 16; l++) {
        v[l] = expf(v[l] - mx);
        s += v[l];
    }
#pragma unroll
    for (int o = 16; o; o >>= 1) s += __shfl_xor_sync(0xffffffffu, s, o);
    __syncthreads();
    if (!lane) red[wid] = s;
    __syncthreads();
    s = 0.f;
#pragma unroll
    for (int w = 0; w < 8; w++) s += red[w];
    float inv = 1.0f / s;
#pragma unroll
    for (int l = 0; l < 16; l++) p[tid + l * 256] = v[l] * inv;
}

// ---------------------------------------------------------------------------
// K4: Lc partials + reduce
// ---------------------------------------------------------------------------
__global__ __launch_bounds__(256) void lc_partial_kernel() {
    __shared__ float ks[16][64];
    __shared__ float vsm[64][65];
    const int s = blockIdx.x, u = blockIdx.y, b = blockIdx.z;
    const int tid = threadIdx.x;
    const int kk = tid >> 4, vg = tid & 15;
    float acc[4] = {0.f, 0.f, 0.f, 0.f};
    const float* kbase = g_proj + ((size_t)b * 384 + 64 + u * 16) * N_;
    const float* vbase = g_proj + ((size_t)b * 384 + 128 + u * 64) * N_;
    const int m0b = s * 512;

    for (int mc = 0; mc < 512; mc += 64) {
        const int m0 = m0b + mc;
#pragma unroll
        for (int l = 0; l < 4; l++) {
            int e = tid + l * 256;
            ks[e >> 6][e & 63] = kbase[(size_t)(e >> 6) * N_ + m0 + (e & 63)];
        }
#pragma unroll
        for (int l = 0; l < 16; l++) {
            int e = tid + l * 256;
            vsm[e >> 6][e & 63] = vbase[(size_t)(e >> 6) * N_ + m0 + (e & 63)];
        }
        __syncthreads();
#pragma unroll 8
        for (int m = 0; m < 64; m++) {
            float kv = ks[kk][m];
#pragma unroll
            for (int j = 0; j < 4; j++) acc[j] = fmaf(kv, vsm[vg * 4 + j][m], acc[j]);
        }
        __syncthreads();
    }
    float* dst = g_LcPart + (((size_t)b * 4 + u) * 8 + s) * 1024 + kk * 64 + vg * 4;
#pragma unroll
    for (int j = 0; j < 4; j++) dst[j] = acc[j];
}

__global__ void lc_reduce_kernel() {
    const int b = blockIdx.x;
    const int t = threadIdx.x;  // 1024
    float s = 0.f;
#pragma unroll
    for (int p = 0; p < 32; p++) s += g_LcPart[((size_t)b * 32 + p) * 1024 + t];
    g_Lc[b * 1024 + t] = s;
}

// ---------------------------------------------------------------------------
// F0: FFT of position kernel rows (flipped, circularly wrapped).
// Writes Karatsuba-form table g_W3[row*65+f] = (c, d-c, c+d, 0).
// ---------------------------------------------------------------------------
__global__ __launch_bounds__(256) void what_kernel(const float* __restrict__ w_pos) {
    __shared__ float2 lines[8][128];
    const int wid = threadIdx.x >> 5, lane = threadIdx.x & 31;
    const int row = blockIdx.x * 8 + wid;
    if (row >= 1472) return;
    const int k = row / 92;
    const int rem = row - k * 92;
    const int u = rem / 23;
    const int dy = rem - u * 23;
    float2* ln = lines[wid];
#pragma unroll
    for (int t = 0; t < 4; t++) ln[lane + t * 32] = make_float2(0.f, 0.f);
    __syncwarp();
    if (lane < 23) {
        float w = w_pos[(size_t)(k * 4 + u) * 529 + dy * 23 + lane];
        ln[(11 - lane) & 127] = make_float2(w, 0.f);
    }
    warp_fft128(ln, lane);
#pragma unroll
    for (int t = 0; t < 2; t++) {
        int f = lane + t * 32;
        float2 w = ln[f];
        g_W3[(size_t)row * 65 + f] = make_float4(w.x, w.y - w.x, w.x + w.y, 0.f);
    }
    if (lane == 0) {
        float2 w = ln[64];
        g_W3[(size_t)row * 65 + 64] = make_float4(w.x, w.y - w.x, w.x + w.y, 0.f);
    }
}

// ---------------------------------------------------------------------------
// F1: forward FFT of v rows (zero-padded 64->128). Store bins 0..64.
// ---------------------------------------------------------------------------
__global__ __launch_bounds__(256) void rhat_kernel() {
    __shared__ float2 lines[8][128];
    const int wid = threadIdx.x >> 5, lane = threadIdx.x & 31;
    const int r = blockIdx.x * 8 + wid;
    const int y  = r & 63;
    const int u  = (r >> 6) & 3;
    const int dv = (r >> 8) & 63;
    const int b  = r >> 14;
    const float* src = g_proj + ((size_t)(b * 384 + 128 + u * 64 + dv)) * N_ + y * 64;
    float2* ln = lines[wid];
    ln[lane]      = make_float2(src[lane], 0.f);
    ln[lane + 32] = make_float2(src[lane + 32], 0.f);
    ln[lane + 64] = make_float2(0.f, 0.f);
    ln[lane + 96] = make_float2(0.f, 0.f);
    warp_fft128(ln, lane);
    float2* dst = g_Rhat + (size_t)r * 65;
    dst[lane]      = ln[lane];
    dst[lane + 32] = ln[lane + 32];
    if (lane == 0) dst[64] = ln[64];
}

// ---------------------------------------------------------------------------
// MEGA fused: frequency mix (Karatsuba) + inverse FFT + final combine.
// block = (dv, b), 512 thr, 16 warps. 8 y-tiles of 8 rows each.
// smem: Gs 8320 f2 + Rs 7800 f2 + Ss 7800 f = 160,160 B.
// ---------------------------------------------------------------------------
__global__ __launch_bounds__(512) void mega_kernel(const float* __restrict__ b_pos,
                                                   float* __restrict__ out) {
    extern __shared__ float2 sm[];
    float2* Gs = sm;                        // 8320 float2
    float2* Rs = sm + 8320;                 // 7800 float2 (ab)
    float*  Ss = (float*)(sm + 16120);      // 7800 float  (a+b)
    const int dv = blockIdx.x, b = blockIdx.y;
    const int tid  = threadIdx.x;
    const int lane = tid & 31;
    const int wrp  = tid >> 5;              // 0..15
    // mix mapping
    const int kq = wrp & 3;
    const int fh = wrp >> 2;                // 0..3
    const int fl = lane & 15;
    const int f  = fh * 16 + fl;            // 0..63
    const int yh = lane >> 4;               // 0..1 -> y rows yh*4..yh*4+3
    const int bdv = b * 64 + dv;
    // nyquist mapping (threads 0..127)
    const int c_y = tid >> 4, c_k = tid & 15;
    // inverse mapping
    const int kp = wrp & 7;
    const int yb = wrp >> 3;                // 0..1
    const int k0 = kp * 2, k1 = k0 + 1;
    const float add0 = b_pos[k0] + g_Lc[b * 1024 + k0 * 64 + dv];
    const float add1 = b_pos[k1] + g_Lc[b * 1024 + k1 * 64 + dv];
    const float sc = 1.0f / 128.0f;
    float2* Z    = Rs + wrp * 128;          // alias: Rs[0..2047]
    float*  tile = (float*)(Rs + 2048);     // alias: Rs[2048..6143], [16k][512px]
    // combine mapping
    const int px = tid;                     // 0..511

    for (int yt = 0; yt < 8; yt++) {
        const int y0 = yt * 8;
        __syncthreads();                    // previous combine done with tile; Gs free
        // ---- stage Rs halo rows y0-11 .. y0+18 (30 rows) ----
        for (int i = tid; i < 7800; i += 512) {
            int u   = i / 1950;
            int rem = i - u * 1950;
            int rr  = rem / 65;
            int ff  = rem - rr * 65;
            int y   = y0 + rr - 11;
            float2 val = make_float2(0.f, 0.f);
            if (y >= 0 && y < 64)
                val = g_Rhat[(((size_t)bdv * 4 + u) * 64 + y) * 65 + ff];
            Rs[i] = val;
            Ss[i] = val.x + val.y;
        }
        __syncthreads();

        // ---- mix (Karatsuba): f = 0..63, thread: 4y x 4k ----
        {
            float A1[4][4], A2[4][4], A3[4][4];
#pragma unroll
            for (int i = 0; i < 4; i++)
#pragma unroll
                for (int j = 0; j < 4; j++) { A1[i][j] = 0.f; A2[i][j] = 0.f; A3[i][j] = 0.f; }

#pragma unroll 1
            for (int u = 0; u < 4; u++) {
                const float2* abp = Rs + (u * 30 + yh * 4) * 65 + f;
                const float*  sp  = Ss + (u * 30 + yh * 4) * 65 + f;
                const float4* wp  = g_W3 + ((size_t)(kq * 4) * 92 + u * 23) * 65 + f;
#pragma unroll 2
                for (int dy = 0; dy < 23; dy++) {
                    float4 w0 = wp[(size_t)dy * 65];
                    float4 w1 = wp[(size_t)(dy + 92) * 65];
                    float4 w2 = wp[(size_t)(dy + 184) * 65];
                    float4 w3 = wp[(size_t)(dy + 276) * 65];
#pragma unroll
                    for (int i = 0; i < 4; i++) {
                        float2 ab = abp[(dy + i) * 65];
                        float  s  = sp[(dy + i) * 65];
                        A1[i][0] = fmaf(w0.x, s, A1[i][0]);
                        A2[i][0] = fmaf(w0.y, ab.x, A2[i][0]);
                        A3[i][0] = fmaf(w0.z, ab.y, A3[i][0]);
                        A1[i][1] = fmaf(w1.x, s, A1[i][1]);
                        A2[i][1] = fmaf(w1.y, ab.x, A2[i][1]);
                        A3[i][1] = fmaf(w1.z, ab.y, A3[i][1]);
                        A1[i][2] = fmaf(w2.x, s, A1[i][2]);
                        A2[i][2] = fmaf(w2.y, ab.x, A2[i][2]);
                        A3[i][2] = fmaf(w2.z, ab.y, A3[i][2]);
                        A1[i][3] = fmaf(w3.x, s, A1[i][3]);
                        A2[i][3] = fmaf(w3.y, ab.x, A2[i][3]);
                        A3[i][3] = fmaf(w3.z, ab.y, A3[i][3]);
                    }
                }
            }
            // re = A1 - A3, im = A1 + A2
#pragma unroll
            for (int i = 0; i < 4; i++)
#pragma unroll
                for (int j = 0; j < 4; j++)
                    Gs[((yh * 4 + i) * 16 + kq * 4 + j) * 65 + f] =
                        make_float2(A1[i][j] - A3[i][j], A1[i][j] + A2[i][j]);
        }

        // ---- f = 64 Nyquist bin (threads 0..127, schoolbook) ----
        if (tid < 128) {
            float re = 0.f, im = 0.f;
#pragma unroll 1
            for (int u = 0; u < 4; u++) {
                const float2* abp = Rs + (u * 30 + c_y) * 65 + 64;
                const float4* wp  = g_W3 + ((size_t)c_k * 92 + u * 23) * 65 + 64;
#pragma unroll
                for (int dy = 0; dy < 23; dy++) {
                    float2 ab = abp[dy * 65];
                    float4 w  = wp[(size_t)dy * 65];
                    float c = w.x, d = w.x + w.y;
                    re = fmaf(ab.x, c, re); re = fmaf(-ab.y, d, re);
                    im = fmaf(ab.x, d, im); im = fmaf(ab.y, c, im);
                }
            }
            Gs[(c_y * 16 + c_k) * 65 + 64] = make_float2(re, im);
        }
        __syncthreads();   // Gs complete; Rs region free for Z/tile

        // ---- inverse: warp = (kp, yb), 4 lines ----
#pragma unroll 1
        for (int l = 0; l < 4; l++) {
            const int yl = yb * 4 + l;
            const float2* G0 = Gs + (yl * 16 + k0) * 65;
            const float2* G1 = Gs + (yl * 16 + k1) * 65;
#pragma unroll
            for (int t = 0; t < 4; t++) {
                int ff = lane + t * 32;
                float2 z;
                if (ff <= 64) {
                    float2 a = G0[ff], c = G1[ff];
                    z = make_float2(a.x - c.y, a.y + c.x);
                } else {
                    int g = 128 - ff;
                    float2 a = G0[g], c = G1[g];
                    z = make_float2(a.x + c.y, -a.y + c.x);
                }
                Z[ff] = make_float2(z.x, -z.y);
            }
            warp_fft128(Z, lane);
#pragma unroll
            for (int t = 0; t < 2; t++) {
                int x = lane + t * 32;
                float2 o = Z[x];
                tile[k0 * 512 + yl * 64 + x] = o.x * sc + add0;
                tile[k1 * 512 + yl * 64 + x] = -o.y * sc + add1;
            }
        }
        __syncthreads();   // tile complete

        // ---- combine: out[b, h*64+dv, n] = sum_k q[b,h*16+k,n]*tile[k][px] ----
        {
            const int n = y0 * 64 + px;
            const float* qb = g_proj + (size_t)b * 384 * N_ + n;
#pragma unroll
            for (int h = 0; h < 4; h++) {
                float acc = 0.f;
#pragma unroll
                for (int k = 0; k < 16; k++)
                    acc = fmaf(qb[(size_t)(h * 16 + k) * N_], tile[k * 512 + px], acc);
                out[((size_t)b * 256 + h * 64 + dv) * N_ + n] = acc;
            }
        }
    }
}

// ---------------------------------------------------------------------------
extern "C" void kernel_launch(void* const* d_in, const int* in_sizes, int n_in,
                              void* d_out, int out_size) {
    const float* x     = (const float*)d_in[0];
    const float* w_q   = (const float*)d_in[1];
    const float* w_k   = (const float*)d_in[2];
    const float* w_v   = (const float*)d_in[3];
    const float* gq    = (const float*)d_in[4];
    const float* bq    = (const float*)d_in[5];
    const float* mq    = (const float*)d_in[6];
    const float* vq    = (const float*)d_in[7];
    const float* gv    = (const float*)d_in[8];
    const float* bv    = (const float*)d_in[9];
    const float* mv    = (const float*)d_in[10];
    const float* vvar  = (const float*)d_in[11];
    const float* w_pos = (const float*)d_in[12];
    const float* b_pos = (const float*)d_in[13];
    float* out = (float*)d_out;

    const int MEGA_SMEM = 16120 * sizeof(float2) + 7800 * sizeof(float);  // 160,160 B
    cudaFuncSetAttribute(mega_kernel, cudaFuncAttributeMaxDynamicSharedMemorySize, MEGA_SMEM);

    twiddle_kernel<<<1, 64>>>();
    fold_kernel<<<2, 256>>>(w_q, w_k, w_v, gq, bq, mq, vq, gv, bv, mv, vvar);
    proj_gemm_kernel<<<dim3(32, 6, 16), 256>>>(x);
    softmax_kernel<<<1024, 256>>>();
    lc_partial_kernel<<<dim3(8, 4, 16), 256>>>();
    lc_reduce_kernel<<<16, 1024>>>();
    what_kernel<<<184, 256>>>(w_pos);
    rhat_kernel<<<32768, 256>>>();
    mega_kernel<<<dim3(64, 16), 512, MEGA_SMEM>>>(b_pos, out);
}